// round 11
// baseline (speedup 1.0000x reference)
#include <cuda_runtime.h>

#define NELEM 589824      // 64*96*96
#define NVEC4 147456      // NELEM/4
#define BATCH 2
#define TOPK  2048
#define CAP   4096
#define NBINS 4096        // top-12-bit key histogram
#define NBLK  148
#define NTHR  1024
#define CT    8           // c-tiles of 512
#define JT    8           // j-tiles of 512

// ---------------- device scratch ----------------
__device__ unsigned int        g_hist[BATCH][NBINS];   // zeroed at load; re-zeroed in stage 4
__device__ int                 g_cnt[BATCH];           // zeroed in stage 1
__device__ int                 g_rank[BATCH][CAP];     // zeroed in stage 1
__device__ unsigned int        g_done[BATCH][CT];      // zeroed in stage 1
__device__ unsigned long long  g_cand[BATCH][CAP];
__device__ float               g_out7[BATCH][TOPK][7];
__device__ float               g_lo[BATCH][TOPK][3];
__device__ float               g_hi[BATCH][TOPK][3];
__device__ float               g_vol[BATCH][TOPK];
__device__ unsigned long long  g_mask[BATCH][32][TOPK];   // [word][row]; lower triangle untouched
__device__ unsigned int        g_bar_cnt = 0;
__device__ unsigned int        g_bar_gen = 0;          // monotonic across calls

__device__ __forceinline__ unsigned int fkey(float f) {
    unsigned int b = __float_as_uint(f);
    unsigned int m = ((unsigned int)((int)b >> 31)) | 0x80000000u;
    return b ^ m;
}
__device__ __forceinline__ float fkey_inv(unsigned int u) {
    unsigned int b = (u & 0x80000000u) ? (u ^ 0x80000000u) : ~u;
    return __uint_as_float(b);
}

// software grid barrier (148 blocks, all co-resident, 1 block/SM)
__device__ __forceinline__ void gsync() {
    __syncthreads();
    if (threadIdx.x == 0) {
        volatile unsigned int* genp = &g_bar_gen;
        unsigned int my = *genp;
        __threadfence();
        unsigned int ticket = atomicAdd(&g_bar_cnt, 1u);
        if (ticket == NBLK - 1) {
            g_bar_cnt = 0;
            __threadfence();
            atomicAdd(&g_bar_gen, 1u);
        } else {
            while (*genp == my) { }
        }
        __threadfence();
    }
    __syncthreads();
}

__device__ __forceinline__ void hadd(unsigned int* sh, unsigned int bin) {
    unsigned int m = __match_any_sync(0xFFFFFFFFu, bin);
    if ((threadIdx.x & 31) == (unsigned)(__ffs(m) - 1))
        atomicAdd(&sh[bin], (unsigned int)__popc(m));
}

__global__ void __launch_bounds__(NTHR, 1)
k_all(const float* __restrict__ bboxes, const float* __restrict__ scores,
      float* __restrict__ out) {
    __shared__ __align__(16) unsigned char sbuf[28928];
    const int bid = blockIdx.x, t = threadIdx.x;
    const int myb = bid & 1;                 // batch for hist/gather chunking

    // ============ stage 1: histogram + scratch resets ============
    {
        unsigned int* sh = (unsigned int*)sbuf;
        for (int i = t; i < NBINS; i += NTHR) sh[i] = 0u;
        __syncthreads();
        int chunk = bid >> 1;
        const float4* s = (const float4*)(scores + (size_t)myb * NELEM);
        for (int i = chunk * NTHR + t; i < NVEC4; i += 74 * NTHR) {
            float4 v = s[i];
            hadd(sh, fkey(v.x) >> 20);
            hadd(sh, fkey(v.y) >> 20);
            hadd(sh, fkey(v.z) >> 20);
            hadd(sh, fkey(v.w) >> 20);
        }
        // scratch resets (visible after the coming barrier)
        if (bid == 0 && t < BATCH) g_cnt[t] = 0;
        if (bid == 0 && t >= 32 && t < 32 + BATCH * CT)
            ((unsigned int*)g_done)[t - 32] = 0u;
        if (bid >= 2 && bid < 10) {
            int idx = (bid - 2) * NTHR + t;          // 8*1024 == BATCH*CAP
            ((int*)g_rank)[idx] = 0;
        }
        __syncthreads();
        for (int i = t; i < NBINS; i += NTHR) {
            unsigned int c = sh[i];
            if (c) atomicAdd(&g_hist[myb][i], c);
        }
    }
    gsync();   // B1

    // ============ stage 2: local threshold-bin (every block, own batch) ============
    int thr;
    {
        unsigned int* sbin = (unsigned int*)sbuf;            // 16 KB
        unsigned int* tsum = (unsigned int*)(sbuf + 16384);  // 4 KB
        int* sbb = (int*)(sbuf + 20480);
        uint4 v = ((const uint4*)g_hist[myb])[t];            // bins [4t,4t+4)
        ((uint4*)sbin)[t] = v;
        tsum[t] = v.x + v.y + v.z + v.w;
        __syncthreads();
        if (t < 32) {
            unsigned int s = 0;
            for (int k = 0; k < 32; k++) s += tsum[t * 32 + k];
            unsigned int suf = s;                            // inclusive suffix over lanes
            for (int d = 1; d < 32; d <<= 1) {
                unsigned int x = __shfl_down_sync(0xFFFFFFFFu, suf, d);
                if (t + d < 32) suf += x;
            }
            unsigned int ball = __ballot_sync(0xFFFFFFFFu, suf >= TOPK);
            int L = 31 - __clz(ball);
            if (t == L) {
                unsigned int c = suf - s;
                int T = L * 32;
                for (int k = 31; k >= 0; k--) {
                    c += tsum[L * 32 + k];
                    if (c >= TOPK) { T = L * 32 + k; break; }
                }
                unsigned int c2 = c - tsum[T];
                int bin = 4 * T;
                for (int q = 3; q >= 0; q--) {
                    c2 += sbin[4 * T + q];
                    if (c2 >= TOPK) { bin = 4 * T + q; break; }
                }
                *sbb = bin;
            }
        }
        __syncthreads();
        thr = *sbb;
    }

    // ============ stage 3: gather candidates ============
    {
        int chunk = bid >> 1;
        const float4* s = (const float4*)(scores + (size_t)myb * NELEM);
        for (int i = chunk * NTHR + t; i < NVEC4; i += 74 * NTHR) {
            float4 v = s[i];
            float vv[4] = {v.x, v.y, v.z, v.w};
#pragma unroll
            for (int c = 0; c < 4; c++) {
                unsigned int u = fkey(vv[c]);
                if ((int)(u >> 20) >= thr) {
                    int pos = atomicAdd(&g_cnt[myb], 1);
                    if (pos < CAP) {
                        unsigned int p = (unsigned int)(4 * i + c);
                        g_cand[myb][pos] = ((unsigned long long)u << 32) | (~p);
                    }
                }
            }
        }
    }
    gsync();   // B2

    // ============ stage 4: tiled rank + ticketed scatter/deparametrize ============
    if (bid < BATCH * CT * JT) {                       // 128 jobs
        unsigned long long* tile = (unsigned long long*)sbuf;   // 4 KB
        int* sflag = (int*)(sbuf + 8192);
        int b = bid >> 6, r = bid & 63, ct = r >> 3, jt = r & 7;
        int cnt = __ldcg(&g_cnt[b]); if (cnt > CAP) cnt = CAP;
        if (t < 512) {
            int j = jt * 512 + t;
            tile[t] = (j < cnt) ? __ldcg(&g_cand[b][j]) : 0ULL;  // pad 0 < any real key
        }
        __syncthreads();
        int tc = t & 511, half = t >> 9;
        int c = ct * 512 + tc;
        if (c < cnt) {
            unsigned long long ki = __ldcg(&g_cand[b][c]);
            int rk = 0, base = half * 256;
#pragma unroll 8
            for (int jj = 0; jj < 256; jj++)
                rk += (tile[base + jj] > ki);
            if (rk) atomicAdd(&g_rank[b][c], rk);
        }
        __syncthreads();
        if (t == 0) {
            __threadfence();
            unsigned int v = atomicAdd(&g_done[b][ct], 1u);
            sflag[0] = (v == JT - 1);
            if (sflag[0]) __threadfence();
        }
        __syncthreads();
        if (sflag[0] && t < 512) {
            int c2 = ct * 512 + t;
            if (c2 < cnt) {
                unsigned long long ki = __ldcg(&g_cand[b][c2]);
                int row = __ldcg(&g_rank[b][c2]);
                if (row < TOPK) {
                    unsigned int idx = ~(unsigned int)(ki & 0xFFFFFFFFu);
                    int d = idx / 9216;
                    int rem = idx - d * 9216;
                    int h = rem / 96;
                    int w = rem - h * 96;
                    float coord[3] = { (float)d + 0.5f, (float)h + 0.5f, (float)w + 0.5f };
                    const float* bb = bboxes + (size_t)b * 6 * NELEM + idx;
                    g_out7[b][row][0] = fkey_inv((unsigned int)(ki >> 32));
                    float vol = 1.0f;
#pragma unroll
                    for (int q = 0; q < 3; q++) {
                        float ctr = bb[(size_t)q * NELEM] * 12.0f + coord[q];
                        float sz  = expf(bb[(size_t)(q + 3) * NELEM]) * 12.0f;
                        g_out7[b][row][1 + q] = ctr;
                        g_out7[b][row][4 + q] = sz;
                        float hf = sz * 0.5f;
                        g_lo[b][row][q] = ctr - hf;
                        g_hi[b][row][q] = ctr + hf;
                        vol *= sz;
                    }
                    g_vol[b][row] = vol;
                }
            }
        }
    } else {
        // idle blocks re-zero g_hist for the next call (all reads done pre-B2)
        int idx = (bid - BATCH * CT * JT) * NTHR + t;
        if (idx < BATCH * NBINS) ((unsigned int*)g_hist)[idx] = 0u;
    }
    gsync();   // B3

    // ============ stage 5: IoU bitmask, upper triangle (1056 jobs / 16 per block) ====
    {
        int g = t >> 6, l64 = t & 63;
        int slot = bid * 16 + g;
        bool act = slot < 1056;
        int b = 0, itile = 0, jw = 0;
        if (act) {
            b = slot / 528;
            int r = slot - b * 528;
            int it = 0;
            while (r >= 32 - it) { r -= 32 - it; it++; }
            itile = it; jw = it + r;
        }
        float* sj = (float*)sbuf + g * 448;     // 64 boxes * 7 floats per group
        if (act) {
            int j = jw * 64 + l64;
            sj[l64 * 7 + 0] = g_lo[b][j][0];
            sj[l64 * 7 + 1] = g_lo[b][j][1];
            sj[l64 * 7 + 2] = g_lo[b][j][2];
            sj[l64 * 7 + 3] = g_hi[b][j][0];
            sj[l64 * 7 + 4] = g_hi[b][j][1];
            sj[l64 * 7 + 5] = g_hi[b][j][2];
            sj[l64 * 7 + 6] = g_vol[b][j];
        }
        __syncthreads();
        if (act) {
            int i = itile * 64 + l64;
            float lo0 = g_lo[b][i][0], lo1 = g_lo[b][i][1], lo2 = g_lo[b][i][2];
            float hi0 = g_hi[b][i][0], hi1 = g_hi[b][i][1], hi2 = g_hi[b][i][2];
            float voli = g_vol[b][i];
            int j0 = jw * 64;
            unsigned long long bits = 0ULL;
#pragma unroll 8
            for (int jj = 0; jj < 64; jj++) {
                int j = j0 + jj;
                const float* p = sj + jj * 7;
                float t0 = fmaxf(fminf(hi0, p[3]) - fmaxf(lo0, p[0]), 0.0f);
                float t1 = fmaxf(fminf(hi1, p[4]) - fmaxf(lo1, p[1]), 0.0f);
                float t2 = fmaxf(fminf(hi2, p[5]) - fmaxf(lo2, p[2]), 0.0f);
                float inter = t0 * t1 * t2;
                float uni = voli + p[6] - inter;
                float q = 0.25f * uni;              // exactly representable scale
                bool sup = false;
                if (inter > q) {
                    if (inter < q * 1.000001f) sup = (inter / uni > 0.25f);
                    else                       sup = true;
                }
                if (sup && (j > i)) bits |= (1ULL << jj);
            }
            g_mask[b][jw][i] = bits;
        }
    }
    gsync();   // B4

    // ============ stage 6: greedy reduce + output (blocks 0,1) ============
    if (bid < BATCH) {
        int b = bid;
        unsigned long long (*sdiag)[64] = (unsigned long long (*)[64])sbuf;  // 16 KB
        unsigned long long* skeep = (unsigned long long*)(sbuf + 16384);
        for (int e = t; e < 2048; e += NTHR) {
            int w = e >> 6, r = e & 63;
            sdiag[w][r] = g_mask[b][w][w * 64 + r];
        }
        __syncthreads();
        if (t < 32) {
            int lane = t;
            unsigned long long remv = 0ULL;
            for (int w = 0; w < 32; w++) {
                unsigned long long kept = 0ULL;
                if (lane == w) {
                    unsigned long long a = ~remv;
#pragma unroll 8
                    for (int bit = 0; bit < 64; bit++) {
                        if ((a >> bit) & 1ULL) {
                            kept |= 1ULL << bit;
                            a &= ~sdiag[w][bit];
                        }
                    }
                }
                kept = __shfl_sync(0xFFFFFFFFu, kept, w);
                if (lane >= w) {
                    const unsigned long long* col = &g_mask[b][lane][w * 64];
                    unsigned long long a0 = 0, a1 = 0, a2 = 0, a3 = 0;
#pragma unroll
                    for (int q = 0; q < 64; q += 4) {
                        unsigned long long m0 = col[q], m1 = col[q + 1];
                        unsigned long long m2 = col[q + 2], m3 = col[q + 3];
                        if ((kept >> q) & 1ULL)       a0 |= m0;
                        if ((kept >> (q + 1)) & 1ULL) a1 |= m1;
                        if ((kept >> (q + 2)) & 1ULL) a2 |= m2;
                        if ((kept >> (q + 3)) & 1ULL) a3 |= m3;
                    }
                    remv |= a0 | a1 | a2 | a3;
                }
            }
            skeep[lane] = ~remv;
        }
        __syncthreads();
        for (int row = t; row < TOPK; row += NTHR) {
            bool keep = (skeep[row >> 6] >> (row & 63)) & 1ULL;
            float* o = out + ((size_t)b * TOPK + row) * 7;
#pragma unroll
            for (int c = 0; c < 7; c++) o[c] = keep ? g_out7[b][row][c] : 0.0f;
        }
    }
}

extern "C" void kernel_launch(void* const* d_in, const int* in_sizes, int n_in,
                              void* d_out, int out_size) {
    const float* bboxes = (const float*)d_in[0];   // (2,6,64,96,96)
    const float* scores = (const float*)d_in[1];   // (2,64,96,96)
    float* out = (float*)d_out;                    // (2,2048,7)
    k_all<<<NBLK, NTHR>>>(bboxes, scores, out);
}